// round 1
// baseline (speedup 1.0000x reference)
#include <cuda_runtime.h>
#include <cstddef>

#define BB      8
#define HH      56
#define WW      56
#define CC      192
#define HEADS   6
#define HEAD_DIM 32
#define KK      9
#define NA      486          // KK*KK*HEADS
#define HW      3136
#define NROWS   25088        // BB*HW
#define SCALE_F 0.17677669529663687f  // 32^-0.5

// -------- scratch (device globals; allocation-free) --------
__device__ float g_v[(size_t)NROWS * CC];   // 19.3 MB  value projection
__device__ float g_a[(size_t)NROWS * NA];   // 48.8 MB  attention logits / softmax
__device__ float g_o[(size_t)NROWS * CC];   // 19.3 MB  pre-projection output

// ============================================================
// Generic GEMM: C[M=NROWS, NC] = A[NROWS,192] * B[192,NC] (+bias)
// 64x64 block tile, 256 threads, 4x4 micro-tile, K-chunks of 16
// ============================================================
__global__ void gemm_kernel(const float* __restrict__ A,
                            const float* __restrict__ Bw,
                            const float* __restrict__ bias,
                            float* __restrict__ Cout,
                            int NC)
{
    __shared__ float As[16][64];
    __shared__ float Bs[16][68];   // pad to 68 for bank spread

    const int tid = threadIdx.x;
    const int colBase = blockIdx.x * 64;
    const int rowBase = blockIdx.y * 64;
    const int tx = tid & 15;
    const int ty = tid >> 4;

    // A-load indices: each thread one float4 along K
    const int ar = tid >> 2;          // 0..63 (row in tile)
    const int ak = (tid & 3) << 2;    // 0,4,8,12
    // B-load indices: 4 scalars along N
    const int bk = tid >> 4;          // 0..15 (k in tile)
    const int bn = (tid & 15) << 2;   // 0..60

    float acc[4][4];
#pragma unroll
    for (int i = 0; i < 4; i++)
#pragma unroll
        for (int j = 0; j < 4; j++) acc[i][j] = 0.f;

    for (int kt = 0; kt < CC; kt += 16) {
        // load A tile (transposed into smem)
        float4 av = *(const float4*)&A[(size_t)(rowBase + ar) * CC + kt + ak];
        As[ak + 0][ar] = av.x;
        As[ak + 1][ar] = av.y;
        As[ak + 2][ar] = av.z;
        As[ak + 3][ar] = av.w;
        // load B tile (scalar, guarded: NC=486 is not 4-divisible)
#pragma unroll
        for (int j = 0; j < 4; j++) {
            int c = colBase + bn + j;
            Bs[bk][bn + j] = (c < NC) ? Bw[(size_t)(kt + bk) * NC + c] : 0.f;
        }
        __syncthreads();

#pragma unroll
        for (int kk = 0; kk < 16; kk++) {
            float a0 = As[kk][ty * 4 + 0];
            float a1 = As[kk][ty * 4 + 1];
            float a2 = As[kk][ty * 4 + 2];
            float a3 = As[kk][ty * 4 + 3];
            float b0 = Bs[kk][tx * 4 + 0];
            float b1 = Bs[kk][tx * 4 + 1];
            float b2 = Bs[kk][tx * 4 + 2];
            float b3 = Bs[kk][tx * 4 + 3];
            acc[0][0] += a0 * b0; acc[0][1] += a0 * b1; acc[0][2] += a0 * b2; acc[0][3] += a0 * b3;
            acc[1][0] += a1 * b0; acc[1][1] += a1 * b1; acc[1][2] += a1 * b2; acc[1][3] += a1 * b3;
            acc[2][0] += a2 * b0; acc[2][1] += a2 * b1; acc[2][2] += a2 * b2; acc[2][3] += a2 * b3;
            acc[3][0] += a3 * b0; acc[3][1] += a3 * b1; acc[3][2] += a3 * b2; acc[3][3] += a3 * b3;
        }
        __syncthreads();
    }

#pragma unroll
    for (int i = 0; i < 4; i++) {
        const int r = rowBase + ty * 4 + i;
#pragma unroll
        for (int j = 0; j < 4; j++) {
            const int c = colBase + tx * 4 + j;
            if (c < NC) {
                float val = acc[i][j];
                if (bias) val += bias[c];
                Cout[(size_t)r * NC + c] = val;
            }
        }
    }
}

// ============================================================
// Softmax over consecutive groups of 9 (after *SCALE)
// a layout: [row][head][k][l]  with l fastest -> groups are contiguous
// ============================================================
__global__ void softmax_kernel(float* __restrict__ a)
{
    const long g = (long)blockIdx.x * blockDim.x + threadIdx.x;
    if (g >= (long)NROWS * 54) return;
    float* p = a + g * 9;
    float v[9];
#pragma unroll
    for (int l = 0; l < 9; l++) v[l] = p[l] * SCALE_F;
    float m = v[0];
#pragma unroll
    for (int l = 1; l < 9; l++) m = fmaxf(m, v[l]);
    float s = 0.f;
#pragma unroll
    for (int l = 0; l < 9; l++) { v[l] = __expf(v[l] - m); s += v[l]; }
    const float inv = 1.f / s;
#pragma unroll
    for (int l = 0; l < 9; l++) p[l] = v[l] * inv;
}

// ============================================================
// Fused attention-apply + fold.
//   out[q,h,:] = sum_{k,l valid} a[q-off_k][h][k][l] * v[q-off_k+off_l][h,:]
// Key identity: v position depends only on (l-k) offset, in [-2,2]^2.
// => reduce 81 attention scalars into 25 neighborhood weights first.
// One block = (b, head, 16x16 spatial tile). v tile (+halo 2) in smem.
// ============================================================
__global__ void agg_kernel(const float* __restrict__ a,
                           const float* __restrict__ v,
                           float* __restrict__ o)
{
    extern __shared__ float vsm[];   // 20*20 pixels, stride 33 (conflict-free)

    const int bh = blockIdx.z;
    const int b  = bh / HEADS;
    const int h  = bh - b * HEADS;
    const int ty0 = blockIdx.y * 16;
    const int tx0 = blockIdx.x * 16;
    const int tid = threadIdx.x;

    // cooperative load of v tile+halo for this head (zeros outside image)
    for (int i = tid; i < 20 * 20 * 8; i += 256) {
        const int p = i >> 3;
        const int q = (i & 7) << 2;
        const int sy = p / 20;
        const int sx = p - sy * 20;
        const int gy = ty0 + sy - 2;
        const int gx = tx0 + sx - 2;
        float4 val = make_float4(0.f, 0.f, 0.f, 0.f);
        if (gy >= 0 && gy < HH && gx >= 0 && gx < WW)
            val = *(const float4*)&v[((size_t)(b * HW + gy * WW + gx)) * CC + h * HEAD_DIM + q];
        float* d = &vsm[p * 33 + q];
        d[0] = val.x; d[1] = val.y; d[2] = val.z; d[3] = val.w;
    }
    __syncthreads();

    const int px = tid & 15;
    const int py = tid >> 4;
    const int gy = ty0 + py;
    const int gx = tx0 + px;
    if (gy >= HH || gx >= WW) return;   // no further barriers below

    // reduce 81 softmax values into 25 positional weights
    float w[25];
#pragma unroll
    for (int i = 0; i < 25; i++) w[i] = 0.f;

#pragma unroll
    for (int i = 0; i < 3; i++) {
#pragma unroll
        for (int j = 0; j < 3; j++) {
            const int cy = gy + 1 - i;
            const int cx = gx + 1 - j;
            if (cy < 0 || cy >= HH || cx < 0 || cx >= WW) continue;
            const float* ap = a + ((size_t)(b * HW + cy * WW + cx)) * NA
                                + h * 81 + (i * 3 + j) * 9;
#pragma unroll
            for (int li = 0; li < 3; li++) {
#pragma unroll
                for (int lj = 0; lj < 3; lj++) {
                    w[(li - i + 2) * 5 + (lj - j + 2)] += ap[li * 3 + lj];
                }
            }
        }
    }

    // weighted 5x5 gather of v from smem
    float acc[HEAD_DIM];
#pragma unroll
    for (int d = 0; d < HEAD_DIM; d++) acc[d] = 0.f;

#pragma unroll
    for (int dy = 0; dy < 5; dy++) {
#pragma unroll
        for (int dx = 0; dx < 5; dx++) {
            const float wv = w[dy * 5 + dx];
            const float* vp = &vsm[((py + dy) * 20 + (px + dx)) * 33];
#pragma unroll
            for (int d = 0; d < HEAD_DIM; d++) acc[d] += wv * vp[d];
        }
    }

    float* op = o + ((size_t)(b * HW + gy * WW + gx)) * CC + h * HEAD_DIM;
#pragma unroll
    for (int d = 0; d < HEAD_DIM; d += 4) {
        *(float4*)&op[d] = make_float4(acc[d], acc[d + 1], acc[d + 2], acc[d + 3]);
    }
}

// ============================================================
extern "C" void kernel_launch(void* const* d_in, const int* in_sizes, int n_in,
                              void* d_out, int out_size)
{
    const float* x  = (const float*)d_in[0];
    const float* Wv = (const float*)d_in[1];
    const float* Wa = (const float*)d_in[2];
    const float* ba = (const float*)d_in[3];
    const float* Wp = (const float*)d_in[4];
    const float* bp = (const float*)d_in[5];
    float* out = (float*)d_out;

    float *vp, *ap, *op;
    cudaGetSymbolAddress((void**)&vp, g_v);
    cudaGetSymbolAddress((void**)&ap, g_a);
    cudaGetSymbolAddress((void**)&op, g_o);

    const int smem_agg = 20 * 20 * 33 * sizeof(float);   // 52.8 KB -> opt-in
    cudaFuncSetAttribute(agg_kernel, cudaFuncAttributeMaxDynamicSharedMemorySize, smem_agg);

    // 1) v = x @ Wv
    gemm_kernel<<<dim3(3, NROWS / 64), 256>>>(x, Wv, nullptr, vp, CC);
    // 2) a = x @ Wa + ba
    gemm_kernel<<<dim3(8, NROWS / 64), 256>>>(x, Wa, ba, ap, NA);
    // 3) softmax over groups of 9
    softmax_kernel<<<(NROWS * 54) / 256, 256>>>(ap);
    // 4) fused attention-apply + fold
    agg_kernel<<<dim3(4, 4, BB * HEADS), 256, smem_agg>>>(ap, vp, op);
    // 5) out = o @ Wp + bp
    gemm_kernel<<<dim3(3, NROWS / 64), 256>>>(op, Wp, bp, out, CC);
}

// round 3
// speedup vs baseline: 1.7702x; 1.7702x over previous
#include <cuda_runtime.h>
#include <mma.h>
#include <cstddef>

using namespace nvcuda;

#define BB      8
#define HH      56
#define WW      56
#define CC      192
#define HEADS   6
#define HEAD_DIM 32
#define NA      486
#define HW      3136
#define NROWS   25088
#define SCALE_F 0.17677669529663687f

// -------- scratch (device globals; allocation-free) --------
__device__ float g_v[(size_t)NROWS * CC];   // value projection
__device__ float g_a[(size_t)NROWS * NA];   // attention logits (softmax fused into agg)
__device__ float g_o[(size_t)NROWS * CC];   // pre-projection output

// ============================================================
// TF32 WMMA GEMM: C[NROWS, NC] = A[NROWS,192] * B[192,NC] (+bias)
// Block 128x64, 256 threads (8 warps as 2x4), warp tile 64x16.
// K chunk 32, register-prefetch software pipeline, smem epilogue.
// NOTE: for NC % 4 != 0 (NC=486) B rows are NOT 16B-aligned; element
// index k*NC+col is always even, so float2 (8B) loads are safe.
// ============================================================
#define BM 128
#define BN 64
#define KB 32
#define A_LD 36   // 144B rows: 16B aligned, bank-spread
#define B_LD 68   // 272B rows: 16B aligned

template<int NC, bool HASB>
__global__ void __launch_bounds__(256) gemm_tf32(const float* __restrict__ A,
                                                 const float* __restrict__ Bw,
                                                 const float* __restrict__ bias,
                                                 float* __restrict__ Cout)
{
    __shared__ float sm[BM * B_LD];            // 8704 floats; holds As+Bs, reused as Cs
    float* As = sm;                            // [BM][A_LD]  (4608)
    float* Bs = sm + BM * A_LD;                // [KB][B_LD]  (2176)

    const int tid = threadIdx.x;
    const int wid = tid >> 5;
    const int wm  = wid >> 2;                  // 0..1  (64-row slabs)
    const int wn  = wid & 3;                   // 0..3  (16-col slabs)
    const int rowBase = blockIdx.y * BM;
    const int colBase = blockIdx.x * BN;

    float4 ra[4];
    float4 rb[2];

    auto loadA = [&](int kt) {
#pragma unroll
        for (int p = 0; p < 4; p++) {
            int idx = tid + p * 256;           // 0..1023
            int r  = idx >> 3;                 // 0..127
            int c4 = (idx & 7) << 2;           // 0..28
            ra[p] = *(const float4*)&A[(size_t)(rowBase + r) * CC + kt + c4];
        }
    };
    auto loadB = [&](int kt) {
#pragma unroll
        for (int p = 0; p < 2; p++) {
            int idx = tid + p * 256;           // 0..511
            int k  = idx >> 4;                 // 0..31
            int c4 = (idx & 15) << 2;          // 0..60
            int col = colBase + c4;
            const size_t base = (size_t)(kt + k) * NC + col;
            if ((NC & 3) == 0) {
                // rows 16B-aligned: single float4
                rb[p] = *(const float4*)&Bw[base];
            } else {
                // element index is even -> 8B aligned: two guarded float2
                float4 v = make_float4(0.f, 0.f, 0.f, 0.f);
                if (col + 1 < NC) {
                    float2 lo = *(const float2*)&Bw[base];
                    v.x = lo.x; v.y = lo.y;
                    if (col + 3 < NC) {
                        float2 hi = *(const float2*)&Bw[base + 2];
                        v.z = hi.x; v.w = hi.y;
                    } else if (col + 2 < NC) {
                        v.z = Bw[base + 2];
                    }
                } else if (col < NC) {
                    v.x = Bw[base];
                }
                rb[p] = v;
            }
        }
    };
    auto storeSmem = [&]() {
#pragma unroll
        for (int p = 0; p < 4; p++) {
            int idx = tid + p * 256;
            int r  = idx >> 3;
            int c4 = (idx & 7) << 2;
            *(float4*)&As[r * A_LD + c4] = ra[p];
        }
#pragma unroll
        for (int p = 0; p < 2; p++) {
            int idx = tid + p * 256;
            int k  = idx >> 4;
            int c4 = (idx & 15) << 2;
            *(float4*)&Bs[k * B_LD + c4] = rb[p];
        }
    };

    wmma::fragment<wmma::accumulator, 16, 16, 8, float> cf[4];
#pragma unroll
    for (int f = 0; f < 4; f++) wmma::fill_fragment(cf[f], 0.f);

    loadA(0); loadB(0);
    storeSmem();
    __syncthreads();

#pragma unroll 1
    for (int kt = 0; kt < CC; kt += KB) {
        const bool more = (kt + KB) < CC;
        if (more) { loadA(kt + KB); loadB(kt + KB); }

#pragma unroll
        for (int kk = 0; kk < KB / 8; kk++) {
            wmma::fragment<wmma::matrix_b, 16, 16, 8, wmma::precision::tf32, wmma::row_major> bf;
            wmma::load_matrix_sync(bf, &Bs[(kk * 8) * B_LD + wn * 16], B_LD);
#pragma unroll
            for (int i = 0; i < bf.num_elements; i++) bf.x[i] = wmma::__float_to_tf32(bf.x[i]);
#pragma unroll
            for (int f = 0; f < 4; f++) {
                wmma::fragment<wmma::matrix_a, 16, 16, 8, wmma::precision::tf32, wmma::row_major> af;
                wmma::load_matrix_sync(af, &As[(wm * 64 + f * 16) * A_LD + kk * 8], A_LD);
#pragma unroll
                for (int i = 0; i < af.num_elements; i++) af.x[i] = wmma::__float_to_tf32(af.x[i]);
                wmma::mma_sync(cf[f], af, bf, cf[f]);
            }
        }
        __syncthreads();
        if (more) { storeSmem(); __syncthreads(); }
    }

    // epilogue: stage through smem (reuse), guarded scalar global write + bias
    float* Cs = sm;                            // [BM][B_LD]
#pragma unroll
    for (int f = 0; f < 4; f++)
        wmma::store_matrix_sync(&Cs[(wm * 64 + f * 16) * B_LD + wn * 16], cf[f], B_LD,
                                wmma::mem_row_major);
    __syncthreads();

#pragma unroll
    for (int p = 0; p < (BM * BN) / 256; p++) {
        int idx = tid + p * 256;
        int r = idx >> 6;
        int c = idx & 63;
        int gc = colBase + c;
        if (gc < NC) {
            float v = Cs[r * B_LD + c];
            if (HASB) v += bias[gc];
            Cout[(size_t)(rowBase + r) * NC + gc] = v;
        }
    }
}

// ============================================================
// Fused scale + softmax + attention-apply + fold.
// Each attention 9-group is consumed by exactly ONE output pixel,
// so in-place softmax here has zero recompute and kills a full
// 97MB read+write pass.
// ============================================================
__global__ void agg_kernel(const float* __restrict__ a,
                           const float* __restrict__ v,
                           float* __restrict__ o)
{
    extern __shared__ float vsm[];   // 20*20 pixels, stride 33 (conflict-free)

    const int bh = blockIdx.z;
    const int b  = bh / HEADS;
    const int h  = bh - b * HEADS;
    const int ty0 = blockIdx.y * 16;
    const int tx0 = blockIdx.x * 16;
    const int tid = threadIdx.x;

    // cooperative load of v tile+halo for this head (zeros outside image)
    for (int i = tid; i < 20 * 20 * 8; i += 256) {
        const int p = i >> 3;
        const int q = (i & 7) << 2;
        const int sy = p / 20;
        const int sx = p - sy * 20;
        const int gy = ty0 + sy - 2;
        const int gx = tx0 + sx - 2;
        float4 val = make_float4(0.f, 0.f, 0.f, 0.f);
        if (gy >= 0 && gy < HH && gx >= 0 && gx < WW)
            val = *(const float4*)&v[((size_t)(b * HW + gy * WW + gx)) * CC + h * HEAD_DIM + q];
        float* d = &vsm[p * 33 + q];
        d[0] = val.x; d[1] = val.y; d[2] = val.z; d[3] = val.w;
    }
    __syncthreads();

    const int px = tid & 15;
    const int py = tid >> 4;
    const int gy = ty0 + py;
    const int gx = tx0 + px;
    if (gy >= HH || gx >= WW) return;   // no further barriers below

    // reduce 81 softmaxed logits into 25 positional weights
    float w[25];
#pragma unroll
    for (int i = 0; i < 25; i++) w[i] = 0.f;

#pragma unroll
    for (int i = 0; i < 3; i++) {
#pragma unroll
        for (int j = 0; j < 3; j++) {
            const int cy = gy + 1 - i;
            const int cx = gx + 1 - j;
            if (cy < 0 || cy >= HH || cx < 0 || cx >= WW) continue;
            const float* ap = a + ((size_t)(b * HW + cy * WW + cx)) * NA
                                + h * 81 + (i * 3 + j) * 9;
            float e[9];
            float m = -1e30f;
#pragma unroll
            for (int l = 0; l < 9; l++) { e[l] = ap[l] * SCALE_F; m = fmaxf(m, e[l]); }
            float s = 0.f;
#pragma unroll
            for (int l = 0; l < 9; l++) { e[l] = __expf(e[l] - m); s += e[l]; }
            const float inv = 1.f / s;
#pragma unroll
            for (int li = 0; li < 3; li++) {
#pragma unroll
                for (int lj = 0; lj < 3; lj++) {
                    w[(li - i + 2) * 5 + (lj - j + 2)] += e[li * 3 + lj] * inv;
                }
            }
        }
    }

    // weighted 5x5 gather of v from smem
    float acc[HEAD_DIM];
#pragma unroll
    for (int d = 0; d < HEAD_DIM; d++) acc[d] = 0.f;

#pragma unroll
    for (int dy = 0; dy < 5; dy++) {
#pragma unroll
        for (int dx = 0; dx < 5; dx++) {
            const float wv = w[dy * 5 + dx];
            const float* vp = &vsm[((py + dy) * 20 + (px + dx)) * 33];
#pragma unroll
            for (int d = 0; d < HEAD_DIM; d++) acc[d] += wv * vp[d];
        }
    }

    float* op = o + ((size_t)(b * HW + gy * WW + gx)) * CC + h * HEAD_DIM;
#pragma unroll
    for (int d = 0; d < HEAD_DIM; d += 4) {
        *(float4*)&op[d] = make_float4(acc[d], acc[d + 1], acc[d + 2], acc[d + 3]);
    }
}

// ============================================================
extern "C" void kernel_launch(void* const* d_in, const int* in_sizes, int n_in,
                              void* d_out, int out_size)
{
    const float* x  = (const float*)d_in[0];
    const float* Wv = (const float*)d_in[1];
    const float* Wa = (const float*)d_in[2];
    const float* ba = (const float*)d_in[3];
    const float* Wp = (const float*)d_in[4];
    const float* bp = (const float*)d_in[5];
    float* out = (float*)d_out;

    float *vp, *ap, *op;
    cudaGetSymbolAddress((void**)&vp, g_v);
    cudaGetSymbolAddress((void**)&ap, g_a);
    cudaGetSymbolAddress((void**)&op, g_o);

    const int smem_agg = 20 * 20 * 33 * sizeof(float);   // 52.8 KB -> opt-in
    cudaFuncSetAttribute(agg_kernel, cudaFuncAttributeMaxDynamicSharedMemorySize, smem_agg);

    // 1) v = x @ Wv                 (tensor cores, tf32)
    gemm_tf32<192, false><<<dim3(3, NROWS / BM), 256>>>(x, Wv, nullptr, vp);
    // 2) a = x @ Wa + ba  (logits)  (tensor cores, tf32)
    gemm_tf32<486, true><<<dim3(8, NROWS / BM), 256>>>(x, Wa, ba, ap);
    // 3) fused softmax + attention-apply + fold
    agg_kernel<<<dim3(4, 4, BB * HEADS), 256, smem_agg>>>(ap, vp, op);
    // 4) out = o @ Wp + bp          (tensor cores, tf32)
    gemm_tf32<192, true><<<dim3(3, NROWS / BM), 256>>>(op, Wp, bp, out);
}